// round 16
// baseline (speedup 1.0000x reference)
#include <cuda_runtime.h>
#include <math.h>
#include <stdint.h>

#define NE 8
#define ND 1024
#define NH 2048
#define NO 1024
#define NB 4096

// ---------------- scratch (device globals; no allocation allowed) ----------
__device__ int   g_cnt[NE];
__device__ int   g_tok [NE * NB];
__device__ float g_wt  [NE * NB];
__device__ int   g_slot[NE * NB];
__device__ float g_h1[(size_t)NE * NB * NH];            // tf32-rounded, k-permuted
__device__ float g_h2[(size_t)NE * NB * NH];            // tf32-rounded, k-permuted
__device__ float g_part[(size_t)2 * NB * NO];
__device__ float g_xr   [(size_t)NE * NB * ND];         // tf32-rounded, k-permuted x
__device__ float g_wrin [(size_t)NE * ND * NH];         // WT[e][n][k_phys]
__device__ float g_wrh  [(size_t)NE * NH * NH];
__device__ float g_wrout[(size_t)NE * NH * NO];
__device__ float g_glog [(size_t)NE * NB * 8];

struct XPtrs { const float* p[NE]; };

// ---------------- helpers ---------------------------------------------------
__device__ __forceinline__ uint32_t f2tf(float f) {
    uint32_t r;
    asm("cvt.rna.tf32.f32 %0, %1;" : "=r"(r) : "f"(f));
    return r;
}
__device__ __forceinline__ float rtf(float f) { return __uint_as_float(f2tf(f)); }

__device__ __forceinline__ uint32_t smem_u32(const void* p) {
    uint32_t a;
    asm("{ .reg .u64 t; cvta.to.shared.u64 t, %1; cvt.u32.u64 %0, t; }" : "=r"(a) : "l"(p));
    return a;
}

__device__ __forceinline__ void mma_tf32(float* c, uint32_t a0, uint32_t a1,
                                         uint32_t a2, uint32_t a3,
                                         uint32_t b0, uint32_t b1) {
    asm volatile(
        "mma.sync.aligned.m16n8k8.row.col.f32.tf32.tf32.f32 "
        "{%0,%1,%2,%3}, {%4,%5,%6,%7}, {%8,%9}, {%0,%1,%2,%3};"
        : "+f"(c[0]), "+f"(c[1]), "+f"(c[2]), "+f"(c[3])
        : "r"(a0), "r"(a1), "r"(a2), "r"(a3), "r"(b0), "r"(b1));
}

__device__ __forceinline__ void cpa16(uint32_t dst, const void* src) {
    asm volatile("cp.async.cg.shared.global [%0], [%1], 16;" :: "r"(dst), "l"(src));
}
#define CP_COMMIT() asm volatile("cp.async.commit_group;" ::: "memory")
#define CP_WAIT(n)  asm volatile("cp.async.wait_group %0;" :: "n"(n) : "memory")

// ---------------- reset -----------------------------------------------------
__global__ void reset_kernel() {
    if (threadIdx.x < NE) g_cnt[threadIdx.x] = 0;
}

// ---------------- weight transpose + tf32 round + k-permute -----------------
// WT[e][n][k_phys] = rtf(W[e][k_log][n]); within each 8-block,
// physical p holds logical (p&1)*4 + (p>>1)  (inverse of phi).
__global__ void __launch_bounds__(256)
transpose_w_kernel(const float* __restrict__ W, int sel, int K, int N) {
    float* WT = (sel == 0) ? g_wrin : (sel == 1) ? g_wrh : g_wrout;
    __shared__ float t[32][33];
    const int e = blockIdx.z;
    const float* Wb = W  + (size_t)e * K * N;
    float*       Tb = WT + (size_t)e * K * N;
    const int n0 = blockIdx.x * 32, k0 = blockIdx.y * 32;
    const int tx = threadIdx.x & 31, ty = threadIdx.x >> 5;   // 32 x 8
    #pragma unroll
    for (int j = 0; j < 32; j += 8)
        t[ty + j][tx] = rtf(Wb[(size_t)(k0 + ty + j) * N + n0 + tx]);
    __syncthreads();
    const int lk = (tx & ~7) + ((tx & 1) * 4 + ((tx & 7) >> 1));  // logical k for physical tx
    #pragma unroll
    for (int j = 0; j < 32; j += 8)
        Tb[(size_t)(n0 + ty + j) * K + k0 + tx] = t[lk][ty + j];
}

// ---------------- gating pass A: partial logits + rounded permuted x --------
__global__ void __launch_bounds__(256)
gatep_kernel(XPtrs xp, const float* __restrict__ gw) {
    __shared__ float Xs[64][129];
    __shared__ float Gs[64][8];

    const int tid   = threadIdx.x;
    const int token = tid & 127;
    const int half  = tid >> 7;
    const int tok0  = blockIdx.x * 128;
    const int e     = blockIdx.y;

    float acc[4] = {0.f, 0.f, 0.f, 0.f};
    const float* __restrict__ xe = xp.p[e];

    for (int dc = 0; dc < ND; dc += 64) {
        #pragma unroll
        for (int i = 0; i < 8; ++i) {
            int idx = tid + i * 256;
            int r   = idx >> 4;
            int c   = (idx & 15) * 4;
            float4 v = *(const float4*)&xe[(size_t)(tok0 + r) * ND + dc + c];
            Xs[c + 0][r] = v.x; Xs[c + 1][r] = v.y;
            Xs[c + 2][r] = v.z; Xs[c + 3][r] = v.w;
            // emit tf32-rounded, k-permuted x: logical (c+j) -> phys 2j + (off>>2)
            float* xrow = &g_xr[((size_t)e * NB + tok0 + r) * ND + dc + (c & ~7)];
            const int o = (c & 4) >> 2;
            xrow[o + 0] = rtf(v.x); xrow[o + 2] = rtf(v.y);
            xrow[o + 4] = rtf(v.z); xrow[o + 6] = rtf(v.w);
        }
        if (tid < 128) {
            int r = tid >> 1;
            int c = (tid & 1) * 4;
            float4 v = *(const float4*)&gw[(size_t)(e * ND + dc + r) * NE + c];
            *(float4*)&Gs[r][c] = v;
        }
        __syncthreads();
        #pragma unroll 16
        for (int k = 0; k < 64; ++k) {
            float  a = Xs[k][token];
            float4 g = *(const float4*)&Gs[k][half * 4];
            acc[0] = fmaf(a, g.x, acc[0]);
            acc[1] = fmaf(a, g.y, acc[1]);
            acc[2] = fmaf(a, g.z, acc[2]);
            acc[3] = fmaf(a, g.w, acc[3]);
        }
        __syncthreads();
    }
    float* out = &g_glog[((size_t)e * NB + tok0 + token) * 8 + half * 4];
    #pragma unroll
    for (int j = 0; j < 4; ++j) out[j] = acc[j];
}

// ---------------- gating pass B: reduce + top-2 + scatter -------------------
__global__ void __launch_bounds__(256)
top2_kernel(const float* __restrict__ gb) {
    const int b = blockIdx.x * 256 + threadIdx.x;
    if (b >= NB) return;
    float v[8] = {0.f, 0.f, 0.f, 0.f, 0.f, 0.f, 0.f, 0.f};
    #pragma unroll
    for (int e = 0; e < NE; ++e) {
        const float4* p = (const float4*)&g_glog[((size_t)e * NB + b) * 8];
        float4 a0 = p[0], a1 = p[1];
        v[0] += a0.x; v[1] += a0.y; v[2] += a0.z; v[3] += a0.w;
        v[4] += a1.x; v[5] += a1.y; v[6] += a1.z; v[7] += a1.w;
    }
    #pragma unroll
    for (int j = 0; j < 8; ++j) v[j] += gb[j];
    int i0 = 0;
    #pragma unroll
    for (int j = 1; j < 8; ++j) if (v[j] > v[i0]) i0 = j;
    int i1 = (i0 == 0) ? 1 : 0;
    #pragma unroll
    for (int j = 0; j < 8; ++j) if (j != i0 && j != i1 && v[j] > v[i1]) i1 = j;
    const float t  = expf(v[i1] - v[i0]);
    const float w0 = 1.f / (1.f + t);
    const float w1 = t  / (1.f + t);
    int p0 = atomicAdd(&g_cnt[i0], 1);
    g_tok[i0 * NB + p0] = b; g_wt[i0 * NB + p0] = w0; g_slot[i0 * NB + p0] = 0;
    int p1 = atomicAdd(&g_cnt[i1], 1);
    g_tok[i1 * NB + p1] = b; g_wt[i1 * NB + p1] = w1; g_slot[i1 * NB + p1] = 1;
}

// ---------------- tf32 mma.sync expert GEMM ---------------------------------
// CTA 128(M) x 256(N), 8 warps, warp tile 64x64 (wm 0..1, wn 0..3).
// K-chunk 32, 3-stage cp.async ring, ONE sync per chunk.
// A smem [m][k_phys] stride 40; B smem [n][k_phys] stride 40.
// k-permutation makes fragment (k,k+4) pairs adjacent -> LDS.64, conflict-free
// (stride mod 32 == 8: bank = 8*grp + 2*tig distinct per 16-lane phase).
#define AST 40
#define BST 40
#define AWRD (128 * AST)                 // 5120 words / stage
#define BWRD (256 * BST)                 // 10240 words / stage
#define TOKW 128
#define STAGES 3
#define SMEM_WORDS (TOKW + STAGES * (AWRD + BWRD))   // 46208 words
#define SMEM_BYTES (SMEM_WORDS * 4)                  // 184,832 B

template<int LAYER, int K, int N_TOTAL>
__global__ void __launch_bounds__(256, 1)
expert_mma(const float* __restrict__ bias) {
    const int e   = blockIdx.z;
    const int cnt = g_cnt[e];
    const int m0  = blockIdx.y * 128;
    if (m0 >= cnt) return;
    const int n0  = blockIdx.x * 256;

    extern __shared__ uint32_t sm[];
    int*      s_tok = (int*)sm;
    uint32_t* Asm   = sm + TOKW;
    uint32_t* Bsm   = sm + TOKW + STAGES * AWRD;
    const uint32_t suA = smem_u32(Asm);
    const uint32_t suB = smem_u32(Bsm);

    const int tid  = threadIdx.x;
    const int wid  = tid >> 5;
    const int lane = tid & 31;
    const int wm   = wid & 1;        // 2 warps over M (64 rows each)
    const int wn   = wid >> 1;       // 4 warps over N (64 cols each)
    const int grp  = lane >> 2;
    const int tig  = lane & 3;

    const float* __restrict__ WT =
        ((LAYER == 1) ? g_wrin : (LAYER == 2) ? g_wrh : g_wrout)
        + (size_t)e * K * N_TOTAL;       // [n][k_phys]
    const float* __restrict__ biasb = bias + (size_t)e * N_TOTAL;

    if (LAYER == 1) {
        if (tid < 128) {
            int grow = m0 + tid;
            s_tok[tid] = g_tok[e * NB + ((grow < cnt) ? grow : (cnt - 1))];
        }
        __syncthreads();
    }

    // ---- per-thread cp.async source pointers + smem byte offsets -----------
    const float* asrc[4]; uint32_t adst[4];
    #pragma unroll
    for (int it = 0; it < 4; ++it) {
        int idx = tid + it * 256;          // 1024 float4 = 128 rows x 8
        int row = idx >> 3;
        int c4  = (idx & 7) * 4;
        if (LAYER == 1) {
            asrc[it] = g_xr + ((size_t)e * NB + s_tok[row]) * K + c4;
        } else {
            int rowc = m0 + row; if (rowc >= cnt) rowc = cnt - 1;
            const float* src = (LAYER == 2) ? g_h1 : g_h2;
            asrc[it] = src + ((size_t)e * NB + rowc) * K + c4;
        }
        adst[it] = suA + (uint32_t)(row * AST + c4) * 4u;
    }
    const float* bsrc[8]; uint32_t bdst[8];
    #pragma unroll
    for (int it = 0; it < 8; ++it) {
        int idx = tid + it * 256;          // 2048 float4 = 256 n-rows x 8
        int row = idx >> 3;
        int c4  = (idx & 7) * 4;
        bsrc[it] = WT + (size_t)(n0 + row) * K + c4;
        bdst[it] = suB + (uint32_t)(row * BST + c4) * 4u;
    }

    float acc[4][8][4];
    #pragma unroll
    for (int mt = 0; mt < 4; ++mt)
        #pragma unroll
        for (int nt = 0; nt < 8; ++nt)
            #pragma unroll
            for (int q = 0; q < 4; ++q) acc[mt][nt][q] = 0.f;

    const int T = K / 32;

    #define STAGE(s, k0) do {                                              \
        const uint32_t ao = (uint32_t)(s) * (AWRD * 4u);                   \
        const uint32_t bo = (uint32_t)(s) * (BWRD * 4u);                   \
        _Pragma("unroll")                                                  \
        for (int it = 0; it < 4; ++it)                                     \
            cpa16(adst[it] + ao, asrc[it] + (k0));                         \
        _Pragma("unroll")                                                  \
        for (int it = 0; it < 8; ++it)                                     \
            cpa16(bdst[it] + bo, bsrc[it] + (k0));                         \
    } while (0)

    STAGE(0, 0);  CP_COMMIT();
    STAGE(1, 32); CP_COMMIT();

    int sidx = 2;                       // next stage slot to fill (mod 3)
    for (int t = 0; t < T; ++t) {
        CP_WAIT(1);                     // stage t resident
        __syncthreads();                // all warps done with buf (t-1); see t
        if (t + 2 < T) STAGE(sidx, (t + 2) * 32);
        CP_COMMIT();                    // uniform group count
        sidx = (sidx == 2) ? 0 : sidx + 1;

        const uint32_t* As = Asm + (t % 3) * AWRD;
        const uint32_t* Bs = Bsm + (t % 3) * BWRD;
        #pragma unroll
        for (int kk = 0; kk < 4; ++kk) {
            const int acol = kk * 8 + 2 * tig;
            uint2 a[4][2];
            #pragma unroll
            for (int mt = 0; mt < 4; ++mt) {
                const uint32_t* ap = As + (wm * 64 + mt * 16 + grp) * AST + acol;
                a[mt][0] = *(const uint2*)ap;              // (a0, a2)
                a[mt][1] = *(const uint2*)(ap + 8 * AST);  // (a1, a3)
            }
            #pragma unroll
            for (int nt = 0; nt < 8; ++nt) {
                const int nn = wn * 64 + nt * 8 + grp;
                uint2 b = *(const uint2*)(Bs + nn * BST + acol);   // (b0, b1)
                #pragma unroll
                for (int mt = 0; mt < 4; ++mt)
                    mma_tf32(acc[mt][nt],
                             a[mt][0].x, a[mt][1].x, a[mt][0].y, a[mt][1].y,
                             b.x, b.y);
            }
        }
    }
    #undef STAGE

    // ---- epilogue ----------------------------------------------------------
    #pragma unroll
    for (int mt = 0; mt < 4; ++mt) {
        #pragma unroll
        for (int hf = 0; hf < 2; ++hf) {
            const int r = m0 + wm * 64 + mt * 16 + grp + hf * 8;
            if (r >= cnt) continue;
            if (LAYER == 3) {
                const int   li   = e * NB + r;
                const int   tok  = g_tok[li];
                const float wgt  = g_wt[li];
                const int   slot = g_slot[li];
                float* orow = g_part + ((size_t)slot * NB + tok) * NO;
                #pragma unroll
                for (int nt = 0; nt < 8; ++nt) {
                    const int c = n0 + wn * 64 + nt * 8 + tig * 2;
                    float2 bv = *(const float2*)&biasb[c];
                    float2 v;
                    v.x = wgt * (acc[mt][nt][hf * 2 + 0] + bv.x);
                    v.y = wgt * (acc[mt][nt][hf * 2 + 1] + bv.y);
                    *(float2*)&orow[c] = v;
                }
            } else {
                float* hrow = ((LAYER == 1) ? g_h1 : g_h2)
                            + ((size_t)e * NB + r) * N_TOTAL;
                #pragma unroll
                for (int nt = 0; nt < 8; ++nt) {
                    const int c = n0 + wn * 64 + nt * 8 + tig * 2;   // logical
                    float2 bv = *(const float2*)&biasb[c];
                    // k-permuted store: logical pair (c, c+1) -> phys (q, q+2)
                    const int b8 = c & 7;                            // 0,2,4,6
                    const int q  = 2 * (b8 & 3) + (b8 >> 2);
                    float* hb = hrow + (c & ~7);
                    hb[q]     = rtf(fmaxf(acc[mt][nt][hf * 2 + 0] + bv.x, 0.f));
                    hb[q + 2] = rtf(fmaxf(acc[mt][nt][hf * 2 + 1] + bv.y, 0.f));
                }
            }
        }
    }
}

// ---------------- combine ----------------------------------------------------
__global__ void combine_kernel(float* __restrict__ out) {
    const size_t n4 = (size_t)NB * NO / 4;
    const float4* p0 = (const float4*)g_part;
    const float4* p1 = (const float4*)(g_part + (size_t)NB * NO);
    float4* o = (float4*)out;
    for (size_t i = blockIdx.x * blockDim.x + threadIdx.x; i < n4;
         i += (size_t)gridDim.x * blockDim.x) {
        float4 a = p0[i], b = p1[i];
        float4 r;
        r.x = a.x + b.x; r.y = a.y + b.y; r.z = a.z + b.z; r.w = a.w + b.w;
        o[i] = r;
    }
}

// ---------------- launch -----------------------------------------------------
extern "C" void kernel_launch(void* const* d_in, const int* in_sizes, int n_in,
                              void* d_out, int out_size) {
    XPtrs xp;
    for (int i = 0; i < NE; ++i) xp.p[i] = (const float*)d_in[i];
    const float* gw    = (const float*)d_in[8];
    const float* gb    = (const float*)d_in[9];
    const float* w_in  = (const float*)d_in[10];
    const float* b_in  = (const float*)d_in[11];
    const float* w_h   = (const float*)d_in[12];
    const float* b_h   = (const float*)d_in[13];
    const float* w_out = (const float*)d_in[14];
    const float* b_out = (const float*)d_in[15];
    float* out = (float*)d_out;

    cudaFuncSetAttribute(expert_mma<1, ND, NH>,
                         cudaFuncAttributeMaxDynamicSharedMemorySize, SMEM_BYTES);
    cudaFuncSetAttribute(expert_mma<2, NH, NH>,
                         cudaFuncAttributeMaxDynamicSharedMemorySize, SMEM_BYTES);
    cudaFuncSetAttribute(expert_mma<3, NH, NO>,
                         cudaFuncAttributeMaxDynamicSharedMemorySize, SMEM_BYTES);

    reset_kernel<<<1, 32>>>();
    transpose_w_kernel<<<dim3(NH / 32, ND / 32, NE), 256>>>(w_in,  0, ND, NH);
    transpose_w_kernel<<<dim3(NH / 32, NH / 32, NE), 256>>>(w_h,   1, NH, NH);
    transpose_w_kernel<<<dim3(NO / 32, NH / 32, NE), 256>>>(w_out, 2, NH, NO);
    gatep_kernel<<<dim3(NB / 128, NE), 256>>>(xp, gw);
    top2_kernel<<<NB / 256, 256>>>(gb);
    expert_mma<1, ND, NH><<<dim3(NH / 256, NB / 128, NE), 256, SMEM_BYTES>>>(b_in);
    expert_mma<2, NH, NH><<<dim3(NH / 256, NB / 128, NE), 256, SMEM_BYTES>>>(b_h);
    expert_mma<3, NH, NO><<<dim3(NO / 256, NB / 128, NE), 256, SMEM_BYTES>>>(b_out);
    combine_kernel<<<2048, 256>>>(out);
}